// round 11
// baseline (speedup 1.0000x reference)
#include <cuda_runtime.h>
#include <cuda_bf16.h>
#include <cstdint>

// Problem constants
#define Dm 1024
#define Hn 16
#define HD 64
#define Bb 8
#define Ss 1024
#define M_ROWS (Bb * Ss)          // 8192

// ---------------------------------------------------------------------------
// Scratch (no runtime allocation allowed)
// ---------------------------------------------------------------------------
__device__ float g_q [(size_t)M_ROWS * Dm];          // fp32 q for flash
__device__ float g_kv[(size_t)M_ROWS * 2 * Dm];      // fp32 kv for flash

__device__ __nv_bfloat16 g_qs_hi[(size_t)M_ROWS * Dm];
__device__ __nv_bfloat16 g_qs_lo[(size_t)M_ROWS * Dm];
__device__ __nv_bfloat16 g_vs_hi[(size_t)M_ROWS * Dm];
__device__ __nv_bfloat16 g_vs_lo[(size_t)M_ROWS * Dm];
__device__ __nv_bfloat16 g_hh  [(size_t)M_ROWS * Dm];   // heads hi (from flash)
__device__ __nv_bfloat16 g_hl  [(size_t)M_ROWS * Dm];   // heads lo

__device__ __nv_bfloat16 g_WqT_h [(size_t)Dm * Dm];     // [N,K] k-major
__device__ __nv_bfloat16 g_WqT_l [(size_t)Dm * Dm];
__device__ __nv_bfloat16 g_WkvT_h[(size_t)2 * Dm * Dm];
__device__ __nv_bfloat16 g_WkvT_l[(size_t)2 * Dm * Dm];
__device__ __nv_bfloat16 g_WoT_h [(size_t)Dm * Dm];
__device__ __nv_bfloat16 g_WoT_l [(size_t)Dm * Dm];

// ===========================================================================
// Helpers
// ===========================================================================
__device__ __forceinline__ uint32_t smem_u32(const void* p) {
    uint32_t a;
    asm("{ .reg .u64 t; cvta.to.shared.u64 t, %1; cvt.u32.u64 %0, t; }" : "=r"(a) : "l"(p));
    return a;
}

#define MMA16816(c, a, b)                                                     \
    asm volatile("mma.sync.aligned.m16n8k16.row.col.f32.bf16.bf16.f32 "       \
        "{%0,%1,%2,%3}, {%4,%5,%6,%7}, {%8,%9}, {%0,%1,%2,%3};"               \
        : "+f"((c)[0]), "+f"((c)[1]), "+f"((c)[2]), "+f"((c)[3])              \
        : "r"((a)[0]), "r"((a)[1]), "r"((a)[2]), "r"((a)[3]),                 \
          "r"((b)[0]), "r"((b)[1]))

#define CP_ASYNC16(dst, src) \
    asm volatile("cp.async.cg.shared.global [%0], [%1], 16;" :: "r"(dst), "l"(src))
#define CP_COMMIT()  asm volatile("cp.async.commit_group;" ::: "memory")
#define CP_WAIT2()   asm volatile("cp.async.wait_group 2;" ::: "memory")

// fp32 pair -> (hi bf16 pair, lo bf16 pair) packed as uint32
__device__ __forceinline__ void split2(float x, float y, uint32_t& hi, uint32_t& lo) {
    __nv_bfloat16 hx = __float2bfloat16(x), hy = __float2bfloat16(y);
    __nv_bfloat16 lx = __float2bfloat16(x - __bfloat162float(hx));
    __nv_bfloat16 ly = __float2bfloat16(y - __bfloat162float(hy));
    hi = (uint32_t)__bfloat16_as_ushort(hx) | ((uint32_t)__bfloat16_as_ushort(hy) << 16);
    lo = (uint32_t)__bfloat16_as_ushort(lx) | ((uint32_t)__bfloat16_as_ushort(ly) << 16);
}

// ===========================================================================
// Conversion kernels (memory-bound, run once per launch)
// ===========================================================================
__global__ __launch_bounds__(256)
void split_rows_kernel(const float* __restrict__ X, __nv_bfloat16* __restrict__ H,
                       __nv_bfloat16* __restrict__ L, int n4)
{
    const int i = blockIdx.x * 256 + threadIdx.x;
    if (i >= n4) return;
    const float4 v = ((const float4*)X)[i];
    uint32_t h0, l0, h1, l1;
    split2(v.x, v.y, h0, l0);
    split2(v.z, v.w, h1, l1);
    ((uint2*)H)[i] = make_uint2(h0, h1);
    ((uint2*)L)[i] = make_uint2(l0, l1);
}

// W[K,N] fp32 -> WT_hi/lo[N,K] bf16 (32x32 smem transpose tiles)
__global__ __launch_bounds__(256)
void split_wT_kernel(const float* __restrict__ W, __nv_bfloat16* __restrict__ TH,
                     __nv_bfloat16* __restrict__ TL, int K, int N)
{
    __shared__ float t[32][33];
    const int k0 = blockIdx.y * 32, n0 = blockIdx.x * 32;
    const int tx = threadIdx.x, ty = threadIdx.y;   // 32 x 8
    #pragma unroll
    for (int i = ty; i < 32; i += 8)
        t[i][tx] = W[(size_t)(k0 + i) * N + n0 + tx];
    __syncthreads();
    #pragma unroll
    for (int i = ty; i < 32; i += 8) {
        const float v = t[tx][i];                   // = W[k0+tx][n0+i]
        const __nv_bfloat16 h = __float2bfloat16(v);
        const __nv_bfloat16 l = __float2bfloat16(v - __bfloat162float(h));
        TH[(size_t)(n0 + i) * K + k0 + tx] = h;
        TL[(size_t)(n0 + i) * K + k0 + tx] = l;
    }
}

// ===========================================================================
// HMMA GEMM + bias, bf16x3, cp.async 3-stage pipeline.
// C[M,N] = (Ah+Al)[M,K] @ ((Bh+Bl)[N,K])^T + bias  (lo*lo dropped)
// CTA tile 128x128, K-chunk 32, 8 warps (2x4), warp tile 64x32.
// Smem: 4 tiles per stage, pitch 40 elems (80 B): conflict-free scalar LDS
// for the m16n8k16 thread map AND 16 B-aligned rows for cp.async.
// ===========================================================================
#define KC 32
#define PITCH 40
#define TILE_E (128 * PITCH)           // 5120 bf16
#define TILE_B (TILE_E * 2)            // 10240 B
#define STAGE_E (4 * TILE_E)
#define STAGE_B (4 * TILE_B)           // 40960 B
#define NSTAGE 3
#define GEMM_SMEM (NSTAGE * STAGE_B)   // 122880 B

__global__ __launch_bounds__(256)
void gemm_split_kernel(const __nv_bfloat16* __restrict__ Ah_g,
                       const __nv_bfloat16* __restrict__ Al_g,
                       const __nv_bfloat16* __restrict__ Bh_g,
                       const __nv_bfloat16* __restrict__ Bl_g,
                       const float* __restrict__ bias, float* __restrict__ C,
                       int N, int K)
{
    extern __shared__ __nv_bfloat16 sm[];
    const uint32_t smb = smem_u32(sm);

    const int tid  = threadIdx.x;
    const int lane = tid & 31;
    const int warp = tid >> 5;
    const int g    = lane >> 2;
    const int tig  = lane & 3;
    const int warp_m0 = (warp >> 2) * 64;
    const int warp_n0 = (warp & 3) * 32;
    const int bm = blockIdx.y * 128;
    const int bn = blockIdx.x * 128;

    float acc[4][4][4];
    #pragma unroll
    for (int t = 0; t < 4; t++)
        #pragma unroll
        for (int u = 0; u < 4; u++)
            #pragma unroll
            for (int r = 0; r < 4; r++) acc[t][u][r] = 0.f;

    // ---- async stage loader: 8 x 16B cp.async per thread ----
    auto issue_stage = [&](int slot, int k0) {
        const uint32_t sb = smb + slot * STAGE_B;
        #pragma unroll
        for (int half = 0; half < 2; half++) {
            const int idx = tid + half * 256;
            const int row = idx >> 2;
            const int c   = idx & 3;
            const uint32_t doff = (uint32_t)(row * 80 + c * 16);
            const size_t ga = (size_t)(bm + row) * K + k0 + c * 8;
            const size_t gb = (size_t)(bn + row) * K + k0 + c * 8;
            CP_ASYNC16(sb + doff,              Ah_g + ga);
            CP_ASYNC16(sb + TILE_B + doff,     Al_g + ga);
            CP_ASYNC16(sb + 2 * TILE_B + doff, Bh_g + gb);
            CP_ASYNC16(sb + 3 * TILE_B + doff, Bl_g + gb);
        }
        CP_COMMIT();
    };

    // ---- compute one K-chunk from a resident stage ----
    auto compute_stage = [&](int slot) {
        const __nv_bfloat16* Ah = sm + slot * STAGE_E;
        const __nv_bfloat16* Al = Ah + TILE_E;
        const __nv_bfloat16* Bh = Al + TILE_E;
        const __nv_bfloat16* Bl = Bh + TILE_E;

        #pragma unroll
        for (int ks = 0; ks < KC; ks += 16) {
            uint32_t af[4][4], bh[4][2], bl[4][2];
            #pragma unroll
            for (int t = 0; t < 4; t++) {
                const __nv_bfloat16* p = Ah + (warp_m0 + t * 16 + g) * PITCH + ks + tig * 2;
                af[t][0] = *(const uint32_t*)p;
                af[t][1] = *(const uint32_t*)(p + 8 * PITCH);
                af[t][2] = *(const uint32_t*)(p + 8);
                af[t][3] = *(const uint32_t*)(p + 8 * PITCH + 8);
            }
            #pragma unroll
            for (int u = 0; u < 4; u++) {
                const __nv_bfloat16* p = Bh + (warp_n0 + u * 8 + g) * PITCH + ks + tig * 2;
                bh[u][0] = *(const uint32_t*)p;
                bh[u][1] = *(const uint32_t*)(p + 8);
                const __nv_bfloat16* q = Bl + (warp_n0 + u * 8 + g) * PITCH + ks + tig * 2;
                bl[u][0] = *(const uint32_t*)q;
                bl[u][1] = *(const uint32_t*)(q + 8);
            }
            // pass 1: hi*hi (16 independent MMAs before any acc reuse)
            #pragma unroll
            for (int t = 0; t < 4; t++)
                #pragma unroll
                for (int u = 0; u < 4; u++)
                    MMA16816(acc[t][u], af[t], bh[u]);
            // pass 2: hi*lo
            #pragma unroll
            for (int t = 0; t < 4; t++)
                #pragma unroll
                for (int u = 0; u < 4; u++)
                    MMA16816(acc[t][u], af[t], bl[u]);
            // pass 3: lo*hi (reload A regs with lo)
            #pragma unroll
            for (int t = 0; t < 4; t++) {
                const __nv_bfloat16* p = Al + (warp_m0 + t * 16 + g) * PITCH + ks + tig * 2;
                af[t][0] = *(const uint32_t*)p;
                af[t][1] = *(const uint32_t*)(p + 8 * PITCH);
                af[t][2] = *(const uint32_t*)(p + 8);
                af[t][3] = *(const uint32_t*)(p + 8 * PITCH + 8);
            }
            #pragma unroll
            for (int t = 0; t < 4; t++)
                #pragma unroll
                for (int u = 0; u < 4; u++)
                    MMA16816(acc[t][u], af[t], bh[u]);
        }
    };

    const int NC = K / KC;   // 32
    issue_stage(0, 0);
    issue_stage(1, KC);
    issue_stage(2, 2 * KC);

    for (int c = 0; c < NC; c++) {
        CP_WAIT2();          // groups 0..c complete (one group committed per iter)
        __syncthreads();
        compute_stage(c % NSTAGE);
        __syncthreads();     // stage c free before overwrite
        if (c + 3 < NC) issue_stage(c % NSTAGE, (c + 3) * KC);
        else            CP_COMMIT();   // empty group keeps wait bookkeeping uniform
    }

    // ---- epilogue: bias + store ----
    #pragma unroll
    for (int t = 0; t < 4; t++) {
        const int r0 = bm + warp_m0 + t * 16 + g;
        #pragma unroll
        for (int u = 0; u < 4; u++) {
            const int cb = bn + warp_n0 + u * 8 + tig * 2;
            const float2 bv = *(const float2*)(bias + cb);
            *(float2*)(C + (size_t)r0 * N + cb) =
                make_float2(acc[t][u][0] + bv.x, acc[t][u][1] + bv.y);
            *(float2*)(C + (size_t)(r0 + 8) * N + cb) =
                make_float2(acc[t][u][2] + bv.x, acc[t][u][3] + bv.y);
        }
    }
}

// ---------------------------------------------------------------------------
// Flash attention, fp32, online softmax. Epilogue writes heads as split
// hi/lo bf16 (feeds the O-projection directly; no fp32 heads pass needed).
// ---------------------------------------------------------------------------
__global__ __launch_bounds__(256, 2)
void flash_kernel(const float* __restrict__ q, const float* __restrict__ kv,
                  __nv_bfloat16* __restrict__ hh, __nv_bfloat16* __restrict__ hl)
{
    __shared__ float Qt[64][68];
    __shared__ float Kt[64][36];
    __shared__ float Vs[32][64];
    __shared__ float Ps[64][33];

    const int bh  = blockIdx.y;
    const int b   = bh >> 4;
    const int h   = bh & 15;
    const int q0  = blockIdx.x * 64;
    const int tid = threadIdx.x;
    const int tx  = tid & 15;
    const int ty  = tid >> 4;

    const float* qb = q  + (size_t)(b * Ss + q0) * Dm + h * HD;
    const float* kb = kv + (size_t)b * Ss * (2 * Dm) + h * HD;
    const float* vb = kb + Dm;

    for (int v = tid; v < 1024; v += 256) {
        const int r = v >> 4;
        const int c = (v & 15) * 4;
        const float4 t = *(const float4*)(qb + (size_t)r * Dm + c);
        Qt[c + 0][r] = t.x; Qt[c + 1][r] = t.y;
        Qt[c + 2][r] = t.z; Qt[c + 3][r] = t.w;
    }

    float m[4], l[4], o[4][4];
    #pragma unroll
    for (int i = 0; i < 4; i++) {
        m[i] = -1e30f; l[i] = 0.f;
        #pragma unroll
        for (int j = 0; j < 4; j++) o[i][j] = 0.f;
    }

    const int kr = tid >> 4;
    const int kc = (tid & 15) * 4;

    for (int kt = 0; kt < Ss; kt += 32) {
        __syncthreads();

        const float4 k0v = *(const float4*)(kb + (size_t)(kt + kr)      * (2 * Dm) + kc);
        const float4 k1v = *(const float4*)(kb + (size_t)(kt + kr + 16) * (2 * Dm) + kc);
        const float4 v0v = *(const float4*)(vb + (size_t)(kt + kr)      * (2 * Dm) + kc);
        const float4 v1v = *(const float4*)(vb + (size_t)(kt + kr + 16) * (2 * Dm) + kc);
        Kt[kc + 0][kr] = k0v.x; Kt[kc + 1][kr] = k0v.y;
        Kt[kc + 2][kr] = k0v.z; Kt[kc + 3][kr] = k0v.w;
        Kt[kc + 0][kr + 16] = k1v.x; Kt[kc + 1][kr + 16] = k1v.y;
        Kt[kc + 2][kr + 16] = k1v.z; Kt[kc + 3][kr + 16] = k1v.w;
        *(float4*)&Vs[kr][kc]      = v0v;
        *(float4*)&Vs[kr + 16][kc] = v1v;
        __syncthreads();

        float s0[4] = {0.f, 0.f, 0.f, 0.f};
        float s1[4] = {0.f, 0.f, 0.f, 0.f};
        #pragma unroll 16
        for (int d = 0; d < 64; d++) {
            const float4 a  = *(const float4*)&Qt[d][ty * 4];
            const float2 bk = *(const float2*)&Kt[d][tx * 2];
            s0[0] = fmaf(a.x, bk.x, s0[0]); s1[0] = fmaf(a.x, bk.y, s1[0]);
            s0[1] = fmaf(a.y, bk.x, s0[1]); s1[1] = fmaf(a.y, bk.y, s1[1]);
            s0[2] = fmaf(a.z, bk.x, s0[2]); s1[2] = fmaf(a.z, bk.y, s1[2]);
            s0[3] = fmaf(a.w, bk.x, s0[3]); s1[3] = fmaf(a.w, bk.y, s1[3]);
        }

        float rm[4];
        #pragma unroll
        for (int i = 0; i < 4; i++) {
            s0[i] *= 0.125f; s1[i] *= 0.125f;
            rm[i] = fmaxf(s0[i], s1[i]);
        }
        #pragma unroll
        for (int off = 8; off; off >>= 1) {
            #pragma unroll
            for (int i = 0; i < 4; i++)
                rm[i] = fmaxf(rm[i], __shfl_xor_sync(0xffffffffu, rm[i], off, 16));
        }

        float rs[4];
        #pragma unroll
        for (int i = 0; i < 4; i++) {
            const float mn    = fmaxf(m[i], rm[i]);
            const float alpha = __expf(m[i] - mn);
            m[i] = mn;
            const float p0 = __expf(s0[i] - mn);
            const float p1 = __expf(s1[i] - mn);
            Ps[ty * 4 + i][tx * 2 + 0] = p0;
            Ps[ty * 4 + i][tx * 2 + 1] = p1;
            rs[i] = p0 + p1;
            l[i] *= alpha;
            o[i][0] *= alpha; o[i][1] *= alpha; o[i][2] *= alpha; o[i][3] *= alpha;
        }
        #pragma unroll
        for (int off = 8; off; off >>= 1) {
            #pragma unroll
            for (int i = 0; i < 4; i++)
                rs[i] += __shfl_xor_sync(0xffffffffu, rs[i], off, 16);
        }
        #pragma unroll
        for (int i = 0; i < 4; i++) l[i] += rs[i];

        __syncthreads();

        #pragma unroll 8
        for (int k2 = 0; k2 < 32; k2++) {
            const float4 vv = *(const float4*)&Vs[k2][tx * 4];
            const float p0 = Ps[ty * 4 + 0][k2];
            const float p1 = Ps[ty * 4 + 1][k2];
            const float p2 = Ps[ty * 4 + 2][k2];
            const float p3 = Ps[ty * 4 + 3][k2];
            o[0][0] = fmaf(p0, vv.x, o[0][0]); o[0][1] = fmaf(p0, vv.y, o[0][1]);
            o[0][2] = fmaf(p0, vv.z, o[0][2]); o[0][3] = fmaf(p0, vv.w, o[0][3]);
            o[1][0] = fmaf(p1, vv.x, o[1][0]); o[1][1] = fmaf(p1, vv.y, o[1][1]);
            o[1][2] = fmaf(p1, vv.z, o[1][2]); o[1][3] = fmaf(p1, vv.w, o[1][3]);
            o[2][0] = fmaf(p2, vv.x, o[2][0]); o[2][1] = fmaf(p2, vv.y, o[2][1]);
            o[2][2] = fmaf(p2, vv.z, o[2][2]); o[2][3] = fmaf(p2, vv.w, o[2][3]);
            o[3][0] = fmaf(p3, vv.x, o[3][0]); o[3][1] = fmaf(p3, vv.y, o[3][1]);
            o[3][2] = fmaf(p3, vv.z, o[3][2]); o[3][3] = fmaf(p3, vv.w, o[3][3]);
        }
    }

    // Normalize, split to bf16 hi/lo, write heads
    #pragma unroll
    for (int i = 0; i < 4; i++) {
        const float inv = 1.f / l[i];
        uint32_t h01, l01, h23, l23;
        split2(o[i][0] * inv, o[i][1] * inv, h01, l01);
        split2(o[i][2] * inv, o[i][3] * inv, h23, l23);
        const size_t off = (size_t)(b * Ss + q0 + ty * 4 + i) * Dm + h * HD + tx * 4;
        *(uint2*)(hh + off) = make_uint2(h01, h23);
        *(uint2*)(hl + off) = make_uint2(l01, l23);
    }
}

// ---------------------------------------------------------------------------
// Launch
// ---------------------------------------------------------------------------
extern "C" void kernel_launch(void* const* d_in, const int* in_sizes, int n_in,
                              void* d_out, int out_size)
{
    const float* query = (const float*)d_in[0];
    const float* value = (const float*)d_in[1];
    const float* Wq    = (const float*)d_in[2];
    const float* bq    = (const float*)d_in[3];
    const float* Wkv   = (const float*)d_in[4];
    const float* bkv   = (const float*)d_in[5];
    const float* Wo    = (const float*)d_in[6];
    const float* bo    = (const float*)d_in[7];
    float* out = (float*)d_out;

    float *qbuf, *kvbuf;
    __nv_bfloat16 *qsh, *qsl, *vsh, *vsl, *hh, *hl;
    __nv_bfloat16 *wqh, *wql, *wkh, *wkl, *woh, *wol;
    cudaGetSymbolAddress((void**)&qbuf,  g_q);
    cudaGetSymbolAddress((void**)&kvbuf, g_kv);
    cudaGetSymbolAddress((void**)&qsh, g_qs_hi);  cudaGetSymbolAddress((void**)&qsl, g_qs_lo);
    cudaGetSymbolAddress((void**)&vsh, g_vs_hi);  cudaGetSymbolAddress((void**)&vsl, g_vs_lo);
    cudaGetSymbolAddress((void**)&hh,  g_hh);     cudaGetSymbolAddress((void**)&hl,  g_hl);
    cudaGetSymbolAddress((void**)&wqh, g_WqT_h);  cudaGetSymbolAddress((void**)&wql, g_WqT_l);
    cudaGetSymbolAddress((void**)&wkh, g_WkvT_h); cudaGetSymbolAddress((void**)&wkl, g_WkvT_l);
    cudaGetSymbolAddress((void**)&woh, g_WoT_h);  cudaGetSymbolAddress((void**)&wol, g_WoT_l);

    cudaFuncSetAttribute(gemm_split_kernel,
                         cudaFuncAttributeMaxDynamicSharedMemorySize, GEMM_SMEM);

    const int n4 = M_ROWS * Dm / 4;   // 2M float4 per activation

    // ---- conversions (memory-bound, ~50us total) ----
    split_rows_kernel<<<(n4 + 255) / 256, 256>>>(query, qsh, qsl, n4);
    split_rows_kernel<<<(n4 + 255) / 256, 256>>>(value, vsh, vsl, n4);
    split_wT_kernel<<<dim3(Dm / 32, Dm / 32),     dim3(32, 8)>>>(Wq,  wqh, wql, Dm, Dm);
    split_wT_kernel<<<dim3(2 * Dm / 32, Dm / 32), dim3(32, 8)>>>(Wkv, wkh, wkl, Dm, 2 * Dm);
    split_wT_kernel<<<dim3(Dm / 32, Dm / 32),     dim3(32, 8)>>>(Wo,  woh, wol, Dm, Dm);

    // ---- projections (tensor cores, cp.async pipeline) ----
    gemm_split_kernel<<<dim3(Dm / 128, M_ROWS / 128), 256, GEMM_SMEM>>>(
        qsh, qsl, wqh, wql, bq, qbuf, Dm, Dm);
    gemm_split_kernel<<<dim3(2 * Dm / 128, M_ROWS / 128), 256, GEMM_SMEM>>>(
        vsh, vsl, wkh, wkl, bkv, kvbuf, 2 * Dm, Dm);

    // ---- attention (writes split heads directly) ----
    flash_kernel<<<dim3(Ss / 64, Bb * Hn), 256>>>(qbuf, kvbuf, hh, hl);

    // ---- output projection ----
    gemm_split_kernel<<<dim3(Dm / 128, M_ROWS / 128), 256, GEMM_SMEM>>>(
        hh, hl, woh, wol, bo, out, Dm, Dm);
}